// round 16
// baseline (speedup 1.0000x reference)
#include <cuda_runtime.h>
#include <cuda_fp16.h>
#include <cstdint>

// Problem constants (fixed instance)
#define BB   4
#define NN   8192
#define KK   16
#define CG   10
#define PP   32768
#define RR   524288
#define NTILES 4096

// ---------------------------------------------------------------------------
// Scratch. Activations AND weights: single fp16 (1-pass mma).
// ---------------------------------------------------------------------------
__device__ float  d_F1[(size_t)PP * 256];        // feat @ w_attn_top (fp32)
__device__ __half d_NB[(size_t)RR * 128];        // neigh (fp16)
__device__ __half d_CAT[(size_t)PP * 384];       // [feat | PL] (fp16)
__device__ __half d_WA[256 * 128];               // w_attn_top^T
__device__ __half d_Wt[256 * 128];               // w_attn_bot^T
__device__ __half d_WSO[256 * 384];              // [w_s*s_s ; w_o*s_o]^T
__device__ int    d_GI[RR];
__device__ int    d_idx64;
__device__ float  d_fold[3][256];   // 0=s_n 1=t_n 2=t_so

__device__ __forceinline__ float lrelu(float x) { return fmaxf(x, 0.2f * x); }

__device__ __forceinline__ uint32_t smem_u32(const void* p) {
    uint32_t a;
    asm("{ .reg .u64 t; cvta.to.shared.u64 t, %1; cvt.u32.u64 %0, t; }" : "=r"(a) : "l"(p));
    return a;
}
__device__ __forceinline__ void ldsm_x4(uint32_t& r0, uint32_t& r1, uint32_t& r2,
                                        uint32_t& r3, uint32_t addr) {
    asm volatile("ldmatrix.sync.aligned.m8n8.x4.shared.b16 {%0,%1,%2,%3}, [%4];"
                 : "=r"(r0), "=r"(r1), "=r"(r2), "=r"(r3) : "r"(addr));
}
#define CP16(dst, src)  asm volatile("cp.async.cg.shared.global [%0], [%1], 16;" :: "r"(dst), "l"(src))
#define CP_COMMIT()     asm volatile("cp.async.commit_group;" ::: "memory")
#define CP_WAIT(n)      asm volatile("cp.async.wait_group %0;" :: "n"(n) : "memory")
#define MMAF16(acc, a, b)                                                     \
    asm volatile("mma.sync.aligned.m16n8k16.row.col.f32.f16.f16.f32 "         \
                 "{%0,%1,%2,%3}, {%4,%5,%6,%7}, {%8,%9}, {%0,%1,%2,%3};"      \
                 : "+f"((acc)[0]), "+f"((acc)[1]), "+f"((acc)[2]), "+f"((acc)[3]) \
                 : "r"((a)[0]), "r"((a)[1]), "r"((a)[2]), "r"((a)[3]),        \
                   "r"((b)[0]), "r"((b)[1]))

// ---------------------------------------------------------------------------
// Launch 0: mega prep (unchanged from R15)
// ---------------------------------------------------------------------------
#define PREP_FEAT_BLKS 1184
__global__ void prep_mega_kernel(
    const float* __restrict__ w_attn, const float* __restrict__ w_s,
    const float* __restrict__ w_o, const float* __restrict__ feat,
    const float* __restrict__ bn_, const float* __restrict__ gn,
    const float* __restrict__ betan, const float* __restrict__ rmn, const float* __restrict__ rvn,
    const float* __restrict__ bo, const float* __restrict__ go,
    const float* __restrict__ betao, const float* __restrict__ rmo, const float* __restrict__ rvo,
    const float* __restrict__ bs, const float* __restrict__ gs,
    const float* __restrict__ betas, const float* __restrict__ rms, const float* __restrict__ rvs,
    const int* __restrict__ widx)
{
    const int b = blockIdx.x, t = threadIdx.x;
    if (b == 0) {
        int i = t;
        if (i < 128) {
            float s = gn[i] * rsqrtf(rvn[i] + 1e-5f);
            d_fold[0][i] = s;
            d_fold[1][i] = (bn_[i] - rmn[i]) * s + betan[i];
        }
        if (i < 256) {
            float so = go[i] * rsqrtf(rvo[i] + 1e-5f);
            float ss = gs[i] * rsqrtf(rvs[i] + 1e-5f);
            d_fold[2][i] = (bo[i] - rmo[i]) * so + betao[i]
                         + (bs[i] - rms[i]) * ss + betas[i];
        }
        return;
    }
    if (b == 1) {
        __shared__ int ok;
        if (t == 0) ok = 1;
        __syncthreads();
        for (int i = t; i < 2048; i += blockDim.x)
            if (widx[2 * i + 1] != 0) ok = 0;
        __syncthreads();
        if (t == 0) d_idx64 = ok;
        return;
    }
    if (b < 130) {
        int i = (b - 2) * 256 + t;
        int n = i >> 7, k = i & 127;
        d_WA[i] = __float2half(w_attn[(size_t)k * 256 + n]);
        return;
    }
    if (b < 258) {
        int i = (b - 130) * 256 + t;
        int n = i >> 7, k = i & 127;
        d_Wt[i] = __float2half(w_attn[(size_t)(128 + k) * 256 + n]);
        return;
    }
    if (b < 642) {
        int i = (b - 258) * 256 + t;
        int n = i / 384, k = i % 384;
        float v;
        if (k < 128) v = w_s[(size_t)k * 256 + n] * (gs[n] * rsqrtf(rvs[n] + 1e-5f));
        else         v = w_o[(size_t)(k - 128) * 256 + n] * (go[n] * rsqrtf(rvo[n] + 1e-5f));
        d_WSO[i] = __float2half(v);
        return;
    }
    for (int i = (b - 642) * 256 + t; i < PP * 128; i += PREP_FEAT_BLKS * 256) {
        int m = i >> 7, k = i & 127;
        d_CAT[(size_t)m * 384 + k] = __float2half(feat[i]);
    }
}

// ---------------------------------------------------------------------------
// Generic HMMA GEMM (fp16 1-pass), BM=64, 3 CTAs/SM (used for out GEMM)
// ---------------------------------------------------------------------------
#define G_SMEM 52224
__global__ __launch_bounds__(256, 3)
void hmma_gemm(const __half* __restrict__ A, int sA,
               const __half* __restrict__ W, int sW,
               float* __restrict__ C, int Kd, int mode, const float* __restrict__ tv)
{
    extern __shared__ __align__(16) char sm[];
    const uint32_t sb = smem_u32(sm);
    const uint32_t aW = sb, aA = sb + 34816;

    const int tid = threadIdx.x;
    const int wid = tid >> 5, lane = tid & 31;
    const int wm = wid >> 2, wn = wid & 3;
    const int g = lane >> 2, tg = lane & 3;
    const int ri = lane & 7, mi = lane >> 3;
    const int m0 = blockIdx.x * 64;
    const int half = blockIdx.y;

    float acc[2][4][4];
#pragma unroll
    for (int i = 0; i < 2; i++)
#pragma unroll
        for (int j = 0; j < 4; j++)
#pragma unroll
            for (int c = 0; c < 4; c++) acc[i][j][c] = 0.f;

    const uint32_t aoff = (uint32_t)((wm * 32 + (mi & 1) * 8 + ri) * 272 + (mi >> 1) * 16);
    const uint32_t boff = (uint32_t)((wn * 32 + (mi >> 1) * 8 + ri) * 272 + (mi & 1) * 16);

    for (int kt = 0; kt < (Kd >> 7); kt++) {
        if (kt > 0) __syncthreads();
        for (int lin = tid; lin < 2048; lin += 256) {
            int row = lin >> 4, ch = lin & 15;
            uint32_t so = row * 272u + ch * 16u;
            size_t wi = (size_t)(half * 128 + row) * sW + kt * 16 + ch;
            CP16(aW + so, (const char*)W + wi * 16);
            if (lin < 1024) {
                size_t ai = (size_t)(m0 + row) * sA + kt * 16 + ch;
                CP16(aA + so, (const char*)A + ai * 16);
            }
        }
        CP_COMMIT();
        CP_WAIT(0);
        __syncthreads();
#pragma unroll
        for (int ks = 0; ks < 8; ks++) {
            const uint32_t k2 = ks * 32;
            uint32_t a[2][4], b[4][2];
            ldsm_x4(a[0][0], a[0][1], a[0][2], a[0][3], aA + aoff + k2);
            ldsm_x4(a[1][0], a[1][1], a[1][2], a[1][3], aA + aoff + 16 * 272 + k2);
            ldsm_x4(b[0][0], b[0][1], b[1][0], b[1][1], aW + boff + k2);
            ldsm_x4(b[2][0], b[2][1], b[3][0], b[3][1], aW + boff + 16 * 272 + k2);
#pragma unroll
            for (int i = 0; i < 2; i++)
#pragma unroll
                for (int j = 0; j < 4; j++)
                    MMAF16(acc[i][j], a[i], b[j]);
        }
    }

#pragma unroll
    for (int i = 0; i < 2; i++) {
        const int row0 = m0 + wm * 32 + i * 16 + g;
#pragma unroll
        for (int j = 0; j < 4; j++) {
            const int col = half * 128 + wn * 32 + j * 8 + 2 * tg;
            float2 v0 = make_float2(acc[i][j][0], acc[i][j][1]);
            float2 v1 = make_float2(acc[i][j][2], acc[i][j][3]);
            if (mode == 3) {
                float t0 = tv[col], t1 = tv[col + 1];
                v0.x = lrelu(v0.x + t0); v0.y = lrelu(v0.y + t1);
                v1.x = lrelu(v1.x + t0); v1.y = lrelu(v1.y + t1);
            }
            *(float2*)(C + (size_t)row0 * 256 + col) = v0;
            *(float2*)(C + (size_t)(row0 + 8) * 256 + col) = v1;
        }
    }
}

// ---------------------------------------------------------------------------
// Launch 1 (merged, overlapping): blocks [0,1024) F1 GEMM; [1024,3072) idx
// conversion; [3072, 3072+NB_BLKS) NB compute (grid-stride).
// ---------------------------------------------------------------------------
#define NB_BLKS 2368
__global__ __launch_bounds__(256, 3)
void mid_kernel(const void* __restrict__ nidx, const float* __restrict__ raw,
                const float* __restrict__ wn_)
{
    const int b = blockIdx.x, t = threadIdx.x;

    if (b < 1024) {
        // --- F1 = CAT[:, :128] @ WA^T  (BM=64, one K chunk) ---
        extern __shared__ __align__(16) char sm[];
        const uint32_t sb = smem_u32(sm);
        const uint32_t aW = sb, aA = sb + 34816;
        const int wid = t >> 5, lane = t & 31;
        const int wm = wid >> 2, wn = wid & 3;
        const int g = lane >> 2, tg = lane & 3;
        const int ri = lane & 7, mi = lane >> 3;
        const int m0 = (b >> 1) * 64;
        const int half = b & 1;

        float acc[2][4][4];
#pragma unroll
        for (int i = 0; i < 2; i++)
#pragma unroll
            for (int j = 0; j < 4; j++)
#pragma unroll
                for (int c = 0; c < 4; c++) acc[i][j][c] = 0.f;

        const uint32_t aoff = (uint32_t)((wm * 32 + (mi & 1) * 8 + ri) * 272 + (mi >> 1) * 16);
        const uint32_t boff = (uint32_t)((wn * 32 + (mi >> 1) * 8 + ri) * 272 + (mi & 1) * 16);

        for (int lin = t; lin < 2048; lin += 256) {
            int row = lin >> 4, ch = lin & 15;
            uint32_t so = row * 272u + ch * 16u;
            CP16(aW + so, (const char*)d_WA + ((size_t)(half * 128 + row) * 16 + ch) * 16);
            if (lin < 1024)
                CP16(aA + so, (const char*)d_CAT + ((size_t)(m0 + row) * 48 + ch) * 16);
        }
        CP_COMMIT();
        CP_WAIT(0);
        __syncthreads();
#pragma unroll
        for (int ks = 0; ks < 8; ks++) {
            const uint32_t k2 = ks * 32;
            uint32_t a[2][4], bb[4][2];
            ldsm_x4(a[0][0], a[0][1], a[0][2], a[0][3], aA + aoff + k2);
            ldsm_x4(a[1][0], a[1][1], a[1][2], a[1][3], aA + aoff + 16 * 272 + k2);
            ldsm_x4(bb[0][0], bb[0][1], bb[1][0], bb[1][1], aW + boff + k2);
            ldsm_x4(bb[2][0], bb[2][1], bb[3][0], bb[3][1], aW + boff + 16 * 272 + k2);
#pragma unroll
            for (int i = 0; i < 2; i++)
#pragma unroll
                for (int j = 0; j < 4; j++)
                    MMAF16(acc[i][j], a[i], bb[j]);
        }
#pragma unroll
        for (int i = 0; i < 2; i++) {
            const int row0 = m0 + wm * 32 + i * 16 + g;
#pragma unroll
            for (int j = 0; j < 4; j++) {
                const int col = half * 128 + wn * 32 + j * 8 + 2 * tg;
                *(float2*)(d_F1 + (size_t)row0 * 256 + col) =
                    make_float2(acc[i][j][0], acc[i][j][1]);
                *(float2*)(d_F1 + (size_t)(row0 + 8) * 256 + col) =
                    make_float2(acc[i][j][2], acc[i][j][3]);
            }
        }
        return;
    }
    if (b < 3072) {
        // --- idx conversion ---
        int r = (b - 1024) * 256 + t;
        long long v;
        if (d_idx64) v = ((const long long*)nidx)[r];
        else         v = (long long)((const int*)nidx)[r];
        int vi = (int)v;
        vi = min(max(vi, 0), NN - 1);
        int batch = r / (NN * KK);
        d_GI[r] = batch * NN + vi;
        return;
    }
    // --- NB compute (grid-stride over row pairs) ---
    const int c = t & 127;
    const int rh = t >> 7;
    float wcol[CG];
#pragma unroll
    for (int g2 = 0; g2 < CG; g2++) wcol[g2] = wn_[g2 * 128 + c];
    const float sc = d_fold[0][c], tc = d_fold[1][c];
    for (int rp = b - 3072; rp < RR / 2; rp += NB_BLKS) {
        int r = rp * 2 + rh;
        const float* rr = raw + (size_t)r * CG;
        float acc = 0.f;
#pragma unroll
        for (int g2 = 0; g2 < CG; g2++) acc += rr[g2] * wcol[g2];
        d_NB[(size_t)r * 128 + c] = __float2half(lrelu(acc * sc + tc));
    }
}

// ---------------------------------------------------------------------------
// Fused LB GEMM + REGISTER softmax/pool. grid = 592, 256 thr, 2 CTAs/SM.
// smem (70656 B): A 0 (2 x 34816) | sgi 69632 (2x512)
// F1 added via direct LDG; softmax/pool via shfl butterfly over g-lanes;
// 2 syncs per tile; pool NB read from current A buffer.
// ---------------------------------------------------------------------------
#define LA_A   0
#define LA_GI  69632
#define LA_TOT 70656

__device__ __forceinline__ void load_a_full(uint32_t sb, int tile, int buf, int tid)
{
    const char* nb = (const char*)d_NB + (size_t)tile * 32768;
    const uint32_t Ab = sb + LA_A + buf * 34816u;
#pragma unroll
    for (int ii = 0; ii < 8; ii++) {
        int lin = tid + 256 * ii;
        int row = lin >> 4, ch = lin & 15;
        CP16(Ab + row * 272u + ch * 16u, nb + (size_t)row * 256 + ch * 16);
    }
    CP_COMMIT();
}
#define BFLY_MAX(x) { x = fmaxf(x, __shfl_xor_sync(0xffffffffu, x, 4));  \
                      x = fmaxf(x, __shfl_xor_sync(0xffffffffu, x, 8));  \
                      x = fmaxf(x, __shfl_xor_sync(0xffffffffu, x, 16)); }
#define BFLY_SUM(x) { x += __shfl_xor_sync(0xffffffffu, x, 4);           \
                      x += __shfl_xor_sync(0xffffffffu, x, 8);           \
                      x += __shfl_xor_sync(0xffffffffu, x, 16); }

__global__ __launch_bounds__(256, 2)
void lb_fused_kernel(const float* __restrict__ feat)
{
    extern __shared__ __align__(16) char sm[];
    const uint32_t sb = smem_u32(sm);
    int* sgi = (int*)(sm + LA_GI);

    const int tid = threadIdx.x;
    const int wid = tid >> 5, lane = tid & 31;
    const int wm = wid >> 1, wn = wid & 1;
    const int g = lane >> 2, tg = lane & 3;
    const int ri = lane & 7, mi = lane >> 3;
    const int q = blockIdx.x & 3;
    const int tile0 = blockIdx.x >> 2;

    // Stage W quarter in A buf 0, pull into registers, then free the buffer.
    for (int lin = tid; lin < 1024; lin += 256) {
        int row = lin >> 4, ch = lin & 15;
        CP16(sb + LA_A + row * 272u + ch * 16u,
             (const char*)d_Wt + ((size_t)(q * 64 + row) * 16 + ch) * 16);
    }
    CP_COMMIT();
    CP_WAIT(0);
    __syncthreads();

    uint32_t bfr[8][4][2];
    {
        const uint32_t boffB = (uint32_t)((wn * 32 + (mi >> 1) * 8 + ri) * 272 + (mi & 1) * 16);
#pragma unroll
        for (int ks = 0; ks < 8; ks++) {
            ldsm_x4(bfr[ks][0][0], bfr[ks][0][1], bfr[ks][1][0], bfr[ks][1][1],
                    sb + LA_A + boffB + ks * 32);
            ldsm_x4(bfr[ks][2][0], bfr[ks][2][1], bfr[ks][3][0], bfr[ks][3][1],
                    sb + LA_A + boffB + 16 * 272 + ks * 32);
        }
    }
    __syncthreads();

    const uint32_t aoff = (uint32_t)((wm * 32 + (mi & 1) * 8 + ri) * 272 + (mi >> 1) * 16);

    load_a_full(sb, tile0, 0, tid);            // pending {A0}

    int it = 0;
    for (int tile = tile0; tile < NTILES; tile += 148, it++) {
        const int cur = it & 1;
        int* sg = sgi + cur * 128;
        if (tid < 128) sg[tid] = d_GI[tile * 128 + tid];
        __syncthreads();                       // sg visible; prev pool reads done

        const int nt = (tile + 148 < NTILES) ? (tile + 148) : tile0;
        load_a_full(sb, nt, cur ^ 1, tid);     // pending {A_cur, A_next}
        CP_WAIT(1);                            // A_cur done
        __syncthreads();

        float acc[2][4][4];
#pragma unroll
        for (int i = 0; i < 2; i++)
#pragma unroll
            for (int j = 0; j < 4; j++)
#pragma unroll
                for (int c = 0; c < 4; c++) acc[i][j][c] = 0.f;

        const uint32_t Abase = sb + LA_A + cur * 34816u + aoff;
#pragma unroll
        for (int ks = 0; ks < 8; ks++) {
            uint32_t a[2][4];
            ldsm_x4(a[0][0], a[0][1], a[0][2], a[0][3], Abase + ks * 32);
            ldsm_x4(a[1][0], a[1][1], a[1][2], a[1][3], Abase + 16 * 272 + ks * 32);
#pragma unroll
            for (int i = 0; i < 2; i++)
#pragma unroll
                for (int j = 0; j < 4; j++)
                    MMAF16(acc[i][j], a[i], bfr[ks][j]);
        }

        // Register softmax + pool (no smem round-trip, no extra syncs)
        const __half* Acur = (const __half*)(sm + LA_A + cur * 34816u);
#pragma unroll
        for (int i = 0; i < 2; i++) {
            const int r0 = wm * 32 + i * 16 + g;
            const int gi0 = sg[r0], gi8 = sg[r0 + 8];
#pragma unroll
            for (int j = 0; j < 4; j++) {
                const int c0 = wn * 32 + j * 8 + 2 * tg;
                float2 f0 = *(const float2*)(d_F1 + (size_t)gi0 * 256 + q * 64 + c0);
                float2 f8 = *(const float2*)(d_F1 + (size_t)gi8 * 256 + q * 64 + c0);
                float lA0 = acc[i][j][0] + f0.x, lB0 = acc[i][j][1] + f0.y;
                float lA8 = acc[i][j][2] + f8.x, lB8 = acc[i][j][3] + f8.y;

                float mA = fmaxf(lA0, lA8), mB = fmaxf(lB0, lB8);
                BFLY_MAX(mA); BFLY_MAX(mB);
                float eA0 = __expf(lA0 - mA), eA8 = __expf(lA8 - mA);
                float eB0 = __expf(lB0 - mB), eB8 = __expf(lB8 - mB);
                float sA = eA0 + eA8, sB = eB0 + eB8;
                BFLY_SUM(sA); BFLY_SUM(sB);

                float vA0, vB0, vA8, vB8;
                if (q < 2) {
                    float2 v0 = *(const float2*)(feat + (size_t)gi0 * 128 + q * 64 + c0);
                    float2 v8 = *(const float2*)(feat + (size_t)gi8 * 128 + q * 64 + c0);
                    vA0 = v0.x; vB0 = v0.y; vA8 = v8.x; vB8 = v8.y;
                } else {
                    float2 v0 = __half22float2(*(const __half2*)(Acur + r0 * 136 + (q - 2) * 64 + c0));
                    float2 v8 = __half22float2(*(const __half2*)(Acur + (r0 + 8) * 136 + (q - 2) * 64 + c0));
                    vA0 = v0.x; vB0 = v0.y; vA8 = v8.x; vB8 = v8.y;
                }
                float pA = eA0 * vA0 + eA8 * vA8;
                float pB = eB0 * vB0 + eB8 * vB8;
                BFLY_SUM(pA); BFLY_SUM(pB);

                if (g == 0) {
                    float outA = pA * __frcp_rn(sA);
                    float outB = pB * __frcp_rn(sB);
                    *(__half2*)(d_CAT + (size_t)(tile * 8 + 2 * wm + i) * 384 +
                                128 + q * 64 + c0) = __floats2half2_rn(outA, outB);
                }
            }
        }
        // loop-top sync protects A buffers / sgi
    }
}

// ---------------------------------------------------------------------------
// Launch
// ---------------------------------------------------------------------------
extern "C" void kernel_launch(void* const* d_in, const int* in_sizes, int n_in,
                              void* d_out, int out_size)
{
    const float* feature = (const float*)d_in[0];
    const float* raw     = (const float*)d_in[1];
    const void*  nidx    = d_in[2];
    const float* w_n     = (const float*)d_in[3];
    const float* b_n     = (const float*)d_in[4];
    const float* g_n     = (const float*)d_in[5];
    const float* beta_n  = (const float*)d_in[6];
    const float* rm_n    = (const float*)d_in[7];
    const float* rv_n    = (const float*)d_in[8];
    const float* w_attn  = (const float*)d_in[9];
    const float* w_o     = (const float*)d_in[10];
    const float* b_o     = (const float*)d_in[11];
    const float* g_o     = (const float*)d_in[12];
    const float* beta_o  = (const float*)d_in[13];
    const float* rm_o    = (const float*)d_in[14];
    const float* rv_o    = (const float*)d_in[15];
    const float* w_s     = (const float*)d_in[16];
    const float* b_s     = (const float*)d_in[17];
    const float* g_s     = (const float*)d_in[18];
    const float* beta_s  = (const float*)d_in[19];
    const float* rm_s    = (const float*)d_in[20];
    const float* rv_s    = (const float*)d_in[21];
    float* out = (float*)d_out;

    float *pFold;
    __half *pCAT, *pWSO;
    cudaGetSymbolAddress((void**)&pFold, d_fold);
    cudaGetSymbolAddress((void**)&pCAT, d_CAT);
    cudaGetSymbolAddress((void**)&pWSO, d_WSO);

    cudaFuncSetAttribute(hmma_gemm, cudaFuncAttributeMaxDynamicSharedMemorySize, G_SMEM);
    cudaFuncSetAttribute(mid_kernel, cudaFuncAttributeMaxDynamicSharedMemorySize, G_SMEM);
    cudaFuncSetAttribute(lb_fused_kernel, cudaFuncAttributeMaxDynamicSharedMemorySize, LA_TOT);

    // 0: prep (fold + detect + weight transposes + feature -> CAT fp16)
    prep_mega_kernel<<<642 + PREP_FEAT_BLKS, 256>>>(
        w_attn, w_s, w_o, feature,
        b_n, g_n, beta_n, rm_n, rv_n,
        b_o, g_o, beta_o, rm_o, rv_o,
        b_s, g_s, beta_s, rm_s, rv_s, (const int*)nidx);
    // 1: merged F1 GEMM + idx conversion + NB (overlapping block ranges)
    mid_kernel<<<3072 + NB_BLKS, 256, G_SMEM>>>(nidx, raw, w_n);
    // 2: fused LB GEMM + register softmax/pool -> CAT[128:384]
    lb_fused_kernel<<<592, 256, LA_TOT>>>(feature);
    // 3: out = lrelu(CAT @ WSO + t_so)
    hmma_gemm<<<dim3(PP / 64, 2), 256, G_SMEM>>>(pCAT, 48, pWSO, 48,
                                                 out, 384, 3, pFold + 2 * 256);
}

// round 17
// speedup vs baseline: 1.1793x; 1.1793x over previous
#include <cuda_runtime.h>
#include <cuda_fp16.h>
#include <cstdint>

// Problem constants (fixed instance)
#define BB   4
#define NN   8192
#define KK   16
#define CG   10
#define PP   32768
#define RR   524288
#define NTILES 4096

// ---------------------------------------------------------------------------
// Scratch. Activations AND weights: single fp16 (1-pass mma).
// ---------------------------------------------------------------------------
__device__ float  d_F1[(size_t)PP * 256];        // feat @ w_attn_top (fp32)
__device__ __half d_NB[(size_t)RR * 128];        // neigh (fp16)
__device__ __half d_CAT[(size_t)PP * 384];       // [feat | PL] (fp16)
__device__ __half d_WA[256 * 128];               // w_attn_top^T
__device__ __half d_Wt[256 * 128];               // w_attn_bot^T
__device__ __half d_WSO[256 * 384];              // [w_s*s_s ; w_o*s_o]^T
__device__ int    d_GI[RR];
__device__ int    d_idx64;
__device__ float  d_fold[3][256];   // 0=s_n 1=t_n 2=t_so

__device__ __forceinline__ float lrelu(float x) { return fmaxf(x, 0.2f * x); }

__device__ __forceinline__ uint32_t smem_u32(const void* p) {
    uint32_t a;
    asm("{ .reg .u64 t; cvta.to.shared.u64 t, %1; cvt.u32.u64 %0, t; }" : "=r"(a) : "l"(p));
    return a;
}
__device__ __forceinline__ void ldsm_x4(uint32_t& r0, uint32_t& r1, uint32_t& r2,
                                        uint32_t& r3, uint32_t addr) {
    asm volatile("ldmatrix.sync.aligned.m8n8.x4.shared.b16 {%0,%1,%2,%3}, [%4];"
                 : "=r"(r0), "=r"(r1), "=r"(r2), "=r"(r3) : "r"(addr));
}
#define CP16(dst, src)  asm volatile("cp.async.cg.shared.global [%0], [%1], 16;" :: "r"(dst), "l"(src))
#define CP_COMMIT()     asm volatile("cp.async.commit_group;" ::: "memory")
#define CP_WAIT(n)      asm volatile("cp.async.wait_group %0;" :: "n"(n) : "memory")
#define MMAF16(acc, a, b)                                                     \
    asm volatile("mma.sync.aligned.m16n8k16.row.col.f32.f16.f16.f32 "         \
                 "{%0,%1,%2,%3}, {%4,%5,%6,%7}, {%8,%9}, {%0,%1,%2,%3};"      \
                 : "+f"((acc)[0]), "+f"((acc)[1]), "+f"((acc)[2]), "+f"((acc)[3]) \
                 : "r"((a)[0]), "r"((a)[1]), "r"((a)[2]), "r"((a)[3]),        \
                   "r"((b)[0]), "r"((b)[1]))

// ---------------------------------------------------------------------------
// Launch 0: mega prep
// ---------------------------------------------------------------------------
#define PREP_FEAT_BLKS 1184
__global__ void prep_mega_kernel(
    const float* __restrict__ w_attn, const float* __restrict__ w_s,
    const float* __restrict__ w_o, const float* __restrict__ feat,
    const float* __restrict__ bn_, const float* __restrict__ gn,
    const float* __restrict__ betan, const float* __restrict__ rmn, const float* __restrict__ rvn,
    const float* __restrict__ bo, const float* __restrict__ go,
    const float* __restrict__ betao, const float* __restrict__ rmo, const float* __restrict__ rvo,
    const float* __restrict__ bs, const float* __restrict__ gs,
    const float* __restrict__ betas, const float* __restrict__ rms, const float* __restrict__ rvs,
    const int* __restrict__ widx)
{
    const int b = blockIdx.x, t = threadIdx.x;
    if (b == 0) {
        int i = t;
        if (i < 128) {
            float s = gn[i] * rsqrtf(rvn[i] + 1e-5f);
            d_fold[0][i] = s;
            d_fold[1][i] = (bn_[i] - rmn[i]) * s + betan[i];
        }
        if (i < 256) {
            float so = go[i] * rsqrtf(rvo[i] + 1e-5f);
            float ss = gs[i] * rsqrtf(rvs[i] + 1e-5f);
            d_fold[2][i] = (bo[i] - rmo[i]) * so + betao[i]
                         + (bs[i] - rms[i]) * ss + betas[i];
        }
        return;
    }
    if (b == 1) {
        __shared__ int ok;
        if (t == 0) ok = 1;
        __syncthreads();
        for (int i = t; i < 2048; i += blockDim.x)
            if (widx[2 * i + 1] != 0) ok = 0;
        __syncthreads();
        if (t == 0) d_idx64 = ok;
        return;
    }
    if (b < 130) {
        int i = (b - 2) * 256 + t;
        int n = i >> 7, k = i & 127;
        d_WA[i] = __float2half(w_attn[(size_t)k * 256 + n]);
        return;
    }
    if (b < 258) {
        int i = (b - 130) * 256 + t;
        int n = i >> 7, k = i & 127;
        d_Wt[i] = __float2half(w_attn[(size_t)(128 + k) * 256 + n]);
        return;
    }
    if (b < 642) {
        int i = (b - 258) * 256 + t;
        int n = i / 384, k = i % 384;
        float v;
        if (k < 128) v = w_s[(size_t)k * 256 + n] * (gs[n] * rsqrtf(rvs[n] + 1e-5f));
        else         v = w_o[(size_t)(k - 128) * 256 + n] * (go[n] * rsqrtf(rvo[n] + 1e-5f));
        d_WSO[i] = __float2half(v);
        return;
    }
    for (int i = (b - 642) * 256 + t; i < PP * 128; i += PREP_FEAT_BLKS * 256) {
        int m = i >> 7, k = i & 127;
        d_CAT[(size_t)m * 384 + k] = __float2half(feat[i]);
    }
}

// ---------------------------------------------------------------------------
// Generic HMMA GEMM (fp16 1-pass), BM=64, 3 CTAs/SM (out GEMM)
// ---------------------------------------------------------------------------
#define G_SMEM 52224
__global__ __launch_bounds__(256, 3)
void hmma_gemm(const __half* __restrict__ A, int sA,
               const __half* __restrict__ W, int sW,
               float* __restrict__ C, int Kd, int mode, const float* __restrict__ tv)
{
    extern __shared__ __align__(16) char sm[];
    const uint32_t sb = smem_u32(sm);
    const uint32_t aW = sb, aA = sb + 34816;

    const int tid = threadIdx.x;
    const int wid = tid >> 5, lane = tid & 31;
    const int wm = wid >> 2, wn = wid & 3;
    const int g = lane >> 2, tg = lane & 3;
    const int ri = lane & 7, mi = lane >> 3;
    const int m0 = blockIdx.x * 64;
    const int half = blockIdx.y;

    float acc[2][4][4];
#pragma unroll
    for (int i = 0; i < 2; i++)
#pragma unroll
        for (int j = 0; j < 4; j++)
#pragma unroll
            for (int c = 0; c < 4; c++) acc[i][j][c] = 0.f;

    const uint32_t aoff = (uint32_t)((wm * 32 + (mi & 1) * 8 + ri) * 272 + (mi >> 1) * 16);
    const uint32_t boff = (uint32_t)((wn * 32 + (mi >> 1) * 8 + ri) * 272 + (mi & 1) * 16);

    for (int kt = 0; kt < (Kd >> 7); kt++) {
        if (kt > 0) __syncthreads();
        for (int lin = tid; lin < 2048; lin += 256) {
            int row = lin >> 4, ch = lin & 15;
            uint32_t so = row * 272u + ch * 16u;
            size_t wi = (size_t)(half * 128 + row) * sW + kt * 16 + ch;
            CP16(aW + so, (const char*)W + wi * 16);
            if (lin < 1024) {
                size_t ai = (size_t)(m0 + row) * sA + kt * 16 + ch;
                CP16(aA + so, (const char*)A + ai * 16);
            }
        }
        CP_COMMIT();
        CP_WAIT(0);
        __syncthreads();
#pragma unroll
        for (int ks = 0; ks < 8; ks++) {
            const uint32_t k2 = ks * 32;
            uint32_t a[2][4], b[4][2];
            ldsm_x4(a[0][0], a[0][1], a[0][2], a[0][3], aA + aoff + k2);
            ldsm_x4(a[1][0], a[1][1], a[1][2], a[1][3], aA + aoff + 16 * 272 + k2);
            ldsm_x4(b[0][0], b[0][1], b[1][0], b[1][1], aW + boff + k2);
            ldsm_x4(b[2][0], b[2][1], b[3][0], b[3][1], aW + boff + 16 * 272 + k2);
#pragma unroll
            for (int i = 0; i < 2; i++)
#pragma unroll
                for (int j = 0; j < 4; j++)
                    MMAF16(acc[i][j], a[i], b[j]);
        }
    }

#pragma unroll
    for (int i = 0; i < 2; i++) {
        const int row0 = m0 + wm * 32 + i * 16 + g;
#pragma unroll
        for (int j = 0; j < 4; j++) {
            const int col = half * 128 + wn * 32 + j * 8 + 2 * tg;
            float2 v0 = make_float2(acc[i][j][0], acc[i][j][1]);
            float2 v1 = make_float2(acc[i][j][2], acc[i][j][3]);
            if (mode == 3) {
                float t0 = tv[col], t1 = tv[col + 1];
                v0.x = lrelu(v0.x + t0); v0.y = lrelu(v0.y + t1);
                v1.x = lrelu(v1.x + t0); v1.y = lrelu(v1.y + t1);
            }
            *(float2*)(C + (size_t)row0 * 256 + col) = v0;
            *(float2*)(C + (size_t)(row0 + 8) * 256 + col) = v1;
        }
    }
}

// ---------------------------------------------------------------------------
// Launch 1 (merged, overlapping): blocks [0,1024) F1 GEMM; [1024,3072) idx
// conversion; [3072, 3072+NB_BLKS) NB compute (grid-stride).
// ---------------------------------------------------------------------------
#define NB_BLKS 2368
__global__ __launch_bounds__(256, 3)
void mid_kernel(const void* __restrict__ nidx, const float* __restrict__ raw,
                const float* __restrict__ wn_)
{
    const int b = blockIdx.x, t = threadIdx.x;

    if (b < 1024) {
        extern __shared__ __align__(16) char sm[];
        const uint32_t sb = smem_u32(sm);
        const uint32_t aW = sb, aA = sb + 34816;
        const int wid = t >> 5, lane = t & 31;
        const int wm = wid >> 2, wn = wid & 3;
        const int g = lane >> 2, tg = lane & 3;
        const int ri = lane & 7, mi = lane >> 3;
        const int m0 = (b >> 1) * 64;
        const int half = b & 1;

        float acc[2][4][4];
#pragma unroll
        for (int i = 0; i < 2; i++)
#pragma unroll
            for (int j = 0; j < 4; j++)
#pragma unroll
                for (int c = 0; c < 4; c++) acc[i][j][c] = 0.f;

        const uint32_t aoff = (uint32_t)((wm * 32 + (mi & 1) * 8 + ri) * 272 + (mi >> 1) * 16);
        const uint32_t boff = (uint32_t)((wn * 32 + (mi >> 1) * 8 + ri) * 272 + (mi & 1) * 16);

        for (int lin = t; lin < 2048; lin += 256) {
            int row = lin >> 4, ch = lin & 15;
            uint32_t so = row * 272u + ch * 16u;
            CP16(aW + so, (const char*)d_WA + ((size_t)(half * 128 + row) * 16 + ch) * 16);
            if (lin < 1024)
                CP16(aA + so, (const char*)d_CAT + ((size_t)(m0 + row) * 48 + ch) * 16);
        }
        CP_COMMIT();
        CP_WAIT(0);
        __syncthreads();
#pragma unroll
        for (int ks = 0; ks < 8; ks++) {
            const uint32_t k2 = ks * 32;
            uint32_t a[2][4], bb[4][2];
            ldsm_x4(a[0][0], a[0][1], a[0][2], a[0][3], aA + aoff + k2);
            ldsm_x4(a[1][0], a[1][1], a[1][2], a[1][3], aA + aoff + 16 * 272 + k2);
            ldsm_x4(bb[0][0], bb[0][1], bb[1][0], bb[1][1], aW + boff + k2);
            ldsm_x4(bb[2][0], bb[2][1], bb[3][0], bb[3][1], aW + boff + 16 * 272 + k2);
#pragma unroll
            for (int i = 0; i < 2; i++)
#pragma unroll
                for (int j = 0; j < 4; j++)
                    MMAF16(acc[i][j], a[i], bb[j]);
        }
#pragma unroll
        for (int i = 0; i < 2; i++) {
            const int row0 = m0 + wm * 32 + i * 16 + g;
#pragma unroll
            for (int j = 0; j < 4; j++) {
                const int col = half * 128 + wn * 32 + j * 8 + 2 * tg;
                *(float2*)(d_F1 + (size_t)row0 * 256 + col) =
                    make_float2(acc[i][j][0], acc[i][j][1]);
                *(float2*)(d_F1 + (size_t)(row0 + 8) * 256 + col) =
                    make_float2(acc[i][j][2], acc[i][j][3]);
            }
        }
        return;
    }
    if (b < 3072) {
        int r = (b - 1024) * 256 + t;
        long long v;
        if (d_idx64) v = ((const long long*)nidx)[r];
        else         v = (long long)((const int*)nidx)[r];
        int vi = (int)v;
        vi = min(max(vi, 0), NN - 1);
        int batch = r / (NN * KK);
        d_GI[r] = batch * NN + vi;
        return;
    }
    const int c = t & 127;
    const int rh = t >> 7;
    float wcol[CG];
#pragma unroll
    for (int g2 = 0; g2 < CG; g2++) wcol[g2] = wn_[g2 * 128 + c];
    const float sc = d_fold[0][c], tc = d_fold[1][c];
    for (int rp = b - 3072; rp < RR / 2; rp += NB_BLKS) {
        int r = rp * 2 + rh;
        const float* rr = raw + (size_t)r * CG;
        float acc = 0.f;
#pragma unroll
        for (int g2 = 0; g2 < CG; g2++) acc += rr[g2] * wcol[g2];
        d_NB[(size_t)r * 128 + c] = __float2half(lrelu(acc * sc + tc));
    }
}

// ---------------------------------------------------------------------------
// Fused LB GEMM (fp16 1-pass, B in registers, whole-tile double-buffered A)
// + smem softmax/pool (R15-proven). grid = 592, 256 thr, 2 CTAs/SM.
// smem (105472 B): Ct 0 (34816; W staged here at startup) |
//                  A 34816 (2 x 34816, stride 272) | sgi 104448 (2x512)
// ---------------------------------------------------------------------------
#define LQ_CT  0
#define LQ_A   34816
#define LQ_GI  104448
#define LQ_TOT 105472

__device__ __forceinline__ void load_a_full(uint32_t sb, int tile, int buf, int tid)
{
    const char* nb = (const char*)d_NB + (size_t)tile * 32768;
    const uint32_t Ab = sb + LQ_A + buf * 34816u;
#pragma unroll
    for (int ii = 0; ii < 8; ii++) {
        int lin = tid + 256 * ii;
        int row = lin >> 4, ch = lin & 15;
        CP16(Ab + row * 272u + ch * 16u, nb + (size_t)row * 256 + ch * 16);
    }
    CP_COMMIT();
}

__global__ __launch_bounds__(256, 2)
void lb_fused_kernel(const float* __restrict__ feat)
{
    extern __shared__ __align__(16) char sm[];
    const uint32_t sb = smem_u32(sm);
    float* Ct = (float*)(sm + LQ_CT);
    int* sgi = (int*)(sm + LQ_GI);

    const int tid = threadIdx.x;
    const int wid = tid >> 5, lane = tid & 31;
    const int wm = wid >> 1, wn = wid & 1;
    const int g = lane >> 2, tg = lane & 3;
    const int ri = lane & 7, mi = lane >> 3;
    const int q = blockIdx.x & 3;
    const int tile0 = blockIdx.x >> 2;

    // W quarter -> Ct region (staging), then into per-warp registers
    for (int lin = tid; lin < 1024; lin += 256) {
        int row = lin >> 4, ch = lin & 15;
        CP16(sb + LQ_CT + row * 272u + ch * 16u,
             (const char*)d_Wt + ((size_t)(q * 64 + row) * 16 + ch) * 16);
    }
    CP_COMMIT();
    CP_WAIT(0);
    __syncthreads();

    uint32_t bfr[8][4][2];
    {
        const uint32_t boffB = (uint32_t)((wn * 32 + (mi >> 1) * 8 + ri) * 272 + (mi & 1) * 16);
#pragma unroll
        for (int ks = 0; ks < 8; ks++) {
            ldsm_x4(bfr[ks][0][0], bfr[ks][0][1], bfr[ks][1][0], bfr[ks][1][1],
                    sb + LQ_CT + boffB + ks * 32);
            ldsm_x4(bfr[ks][2][0], bfr[ks][2][1], bfr[ks][3][0], bfr[ks][3][1],
                    sb + LQ_CT + boffB + 16 * 272 + ks * 32);
        }
    }
    __syncthreads();   // W staging reads done before Ct reuse

    const uint32_t aoff = (uint32_t)((wm * 32 + (mi & 1) * 8 + ri) * 272 + (mi >> 1) * 16);

    load_a_full(sb, tile0, 0, tid);            // pending: {A0}

    int it = 0;
    for (int tile = tile0; tile < NTILES; tile += 148, it++) {
        const int cur = it & 1;
        int* sg = sgi + cur * 128;
        if (tid < 128) sg[tid] = d_GI[tile * 128 + tid];
        __syncthreads();                       // sg visible; prev pool done

        // F1 quarter gather -> Ct             pending: {A_cur, F1}
        const char* F1c = (const char*)d_F1;
#pragma unroll
        for (int ii = 0; ii < 8; ii++) {
            int lin = tid + 256 * ii;
            int r = lin >> 4, c4 = lin & 15;
            int gi = sg[r];
            CP16(sb + LQ_CT + r * 272 + c4 * 16,
                 F1c + (size_t)gi * 1024 + q * 256 + c4 * 16);
        }
        CP_COMMIT();

        // next tile's A into the other buffer pending: {A_cur, F1, A_next}
        const int nt = (tile + 148 < NTILES) ? (tile + 148) : tile0;
        load_a_full(sb, nt, cur ^ 1, tid);

        CP_WAIT(2);                            // A_cur done
        __syncthreads();

        float acc[2][4][4];
#pragma unroll
        for (int i = 0; i < 2; i++)
#pragma unroll
            for (int j = 0; j < 4; j++)
#pragma unroll
                for (int c = 0; c < 4; c++) acc[i][j][c] = 0.f;

        const uint32_t Abase = sb + LQ_A + cur * 34816u + aoff;
#pragma unroll
        for (int ks = 0; ks < 8; ks++) {
            uint32_t a[2][4];
            ldsm_x4(a[0][0], a[0][1], a[0][2], a[0][3], Abase + ks * 32);
            ldsm_x4(a[1][0], a[1][1], a[1][2], a[1][3], Abase + 16 * 272 + ks * 32);
#pragma unroll
            for (int i = 0; i < 2; i++)
#pragma unroll
                for (int j = 0; j < 4; j++)
                    MMAF16(acc[i][j], a[i], bfr[ks][j]);
        }

        CP_WAIT(1);                            // F1 done (A_next still flying)
        __syncthreads();

        // epilogue: Ct += acc (Ct holds gathered F1)
#pragma unroll
        for (int i = 0; i < 2; i++) {
            const int r0 = wm * 32 + i * 16 + g;
#pragma unroll
            for (int j = 0; j < 4; j++) {
                const int c = wn * 32 + j * 8 + 2 * tg;
                float2* p0 = (float2*)(Ct + r0 * 68 + c);
                float2* p1 = (float2*)(Ct + (r0 + 8) * 68 + c);
                float2 v0 = *p0, v1 = *p1;
                v0.x += acc[i][j][0]; v0.y += acc[i][j][1];
                v1.x += acc[i][j][2]; v1.y += acc[i][j][3];
                *p0 = v0; *p1 = v1;
            }
        }
        __syncthreads();                       // Ct complete

        // softmax over K per (point, col) + pool
        const __half* Acur = (const __half*)(sm + LQ_A + cur * 34816u);
#pragma unroll
        for (int s = 0; s < 2; s++) {
            const int pid = tid + 256 * s;
            const int pt = pid >> 6, lc = pid & 63;
            const float* ctp = Ct + pt * 16 * 68 + lc;
            float l[KK];
#pragma unroll
            for (int k = 0; k < KK; k++) l[k] = ctp[k * 68];
            float m = l[0];
#pragma unroll
            for (int k = 1; k < KK; k++) m = fmaxf(m, l[k]);
            float sum = 0.f;
#pragma unroll
            for (int k = 0; k < KK; k++) { l[k] = __expf(l[k] - m); sum += l[k]; }
            float inv = __frcp_rn(sum);

            float pooled = 0.f;
            if (q < 2) {
                const int* gp = sg + pt * 16;
#pragma unroll
                for (int k = 0; k < KK; k++)
                    pooled += l[k] * __ldg(feat + (size_t)gp[k] * 128 + q * 64 + lc);
            } else {
                const __half* ap = Acur + (size_t)(pt * 16) * 136 + (q - 2) * 64 + lc;
#pragma unroll
                for (int k = 0; k < KK; k++)
                    pooled += l[k] * __half2float(ap[k * 136]);
            }
            pooled *= inv;
            d_CAT[(size_t)(tile * 8 + pt) * 384 + 128 + q * 64 + lc] = __float2half(pooled);
        }
        // loop-top sync protects Ct / sg / A buffers
    }
}

// ---------------------------------------------------------------------------
// Launch
// ---------------------------------------------------------------------------
extern "C" void kernel_launch(void* const* d_in, const int* in_sizes, int n_in,
                              void* d_out, int out_size)
{
    const float* feature = (const float*)d_in[0];
    const float* raw     = (const float*)d_in[1];
    const void*  nidx    = d_in[2];
    const float* w_n     = (const float*)d_in[3];
    const float* b_n     = (const float*)d_in[4];
    const float* g_n     = (const float*)d_in[5];
    const float* beta_n  = (const float*)d_in[6];
    const float* rm_n    = (const float*)d_in[7];
    const float* rv_n    = (const float*)d_in[8];
    const float* w_attn  = (const float*)d_in[9];
    const float* w_o     = (const float*)d_in[10];
    const float* b_o     = (const float*)d_in[11];
    const float* g_o     = (const float*)d_in[12];
    const float* beta_o  = (const float*)d_in[13];
    const float* rm_o    = (const float*)d_in[14];
    const float* rv_o    = (const float*)d_in[15];
    const float* w_s     = (const float*)d_in[16];
    const float* b_s     = (const float*)d_in[17];
    const float* g_s     = (const float*)d_in[18];
    const float* beta_s  = (const float*)d_in[19];
    const float* rm_s    = (const float*)d_in[20];
    const float* rv_s    = (const float*)d_in[21];
    float* out = (float*)d_out;

    float *pFold;
    __half *pCAT, *pWSO;
    cudaGetSymbolAddress((void**)&pFold, d_fold);
    cudaGetSymbolAddress((void**)&pCAT, d_CAT);
    cudaGetSymbolAddress((void**)&pWSO, d_WSO);

    cudaFuncSetAttribute(hmma_gemm, cudaFuncAttributeMaxDynamicSharedMemorySize, G_SMEM);
    cudaFuncSetAttribute(mid_kernel, cudaFuncAttributeMaxDynamicSharedMemorySize, G_SMEM);
    cudaFuncSetAttribute(lb_fused_kernel, cudaFuncAttributeMaxDynamicSharedMemorySize, LQ_TOT);

    // 0: prep (fold + detect + weight transposes + feature -> CAT fp16)
    prep_mega_kernel<<<642 + PREP_FEAT_BLKS, 256>>>(
        w_attn, w_s, w_o, feature,
        b_n, g_n, beta_n, rm_n, rv_n,
        b_o, g_o, beta_o, rm_o, rv_o,
        b_s, g_s, beta_s, rm_s, rv_s, (const int*)nidx);
    // 1: merged F1 GEMM + idx conversion + NB (overlapping block ranges)
    mid_kernel<<<3072 + NB_BLKS, 256, G_SMEM>>>(nidx, raw, w_n);
    // 2: fused LB GEMM + smem softmax/pool -> CAT[128:384]
    lb_fused_kernel<<<592, 256, LQ_TOT>>>(feature);
    // 3: out = lrelu(CAT @ WSO + t_so)
    hmma_gemm<<<dim3(PP / 64, 2), 256, G_SMEM>>>(pCAT, 48, pWSO, 48,
                                                 out, 384, 3, pFold + 2 * 256);
}